// round 1
// baseline (speedup 1.0000x reference)
#include <cuda_runtime.h>
#include <math.h>

#define NB      128
#define NNODES  1023
#define NLEAVES 512
#define INDIM   300
#define MEM     300

// -------- static device scratch (no allocations allowed) --------
// C/H state per node: [node][batch][mem]
__device__ float g_C[(size_t)NNODES * NB * MEM];   // ~157 MB
__device__ float g_H[(size_t)NNODES * NB * MEM];   // ~157 MB
// GEMM pre-activation scratch, reused by leaf stage (65536x900) and
// internal levels (max 32768x1500): 58,982,400 floats (~236 MB)
__device__ float g_S[(size_t)NLEAVES * NB * 900];
// combined recurrent weight [600 x 1500] = [Wiouh | Wfh]
__device__ float g_Wcomb[600 * 1500];

__device__ __forceinline__ float sigmoidf_(float x) {
    return 1.0f / (1.0f + __expf(-x));
}

// -------- build combined recurrent weight --------
__global__ void build_wcomb(const float* __restrict__ Wiouh,
                            const float* __restrict__ Wfh) {
    int idx = blockIdx.x * blockDim.x + threadIdx.x;
    if (idx >= 600 * 1500) return;
    int k = idx / 1500, n = idx % 1500;
    g_Wcomb[idx] = (n < 900) ? Wiouh[k * 900 + n] : Wfh[k * 600 + (n - 900)];
}

// -------- leaf GEMM: S[m,n] = inputs[b, leaf, :] @ Wfioux[:, 300+n] --------
// m = leaf*128 + b, M = 65536, K = 300, N = 900
__global__ __launch_bounds__(256) void leaf_gemm(const float* __restrict__ inputs,
                                                 const float* __restrict__ Wfioux) {
    __shared__ float As[20][64];
    __shared__ float Bs[20][64];
    const int m_base = blockIdx.y * 64;
    const int n_base = blockIdx.x * 64;
    const int t = threadIdx.x;
    const int ty = t >> 4, tx = t & 15;
    float acc[4][4] = {};

    for (int k0 = 0; k0 < 300; k0 += 20) {
        #pragma unroll
        for (int j = 0; j < 5; j++) {
            int lin = t + 256 * j;       // 0..1279
            int m = lin / 20, k = lin % 20;
            int row = m_base + m;
            int leaf = row >> 7, b = row & 127;
            As[k][m] = inputs[(size_t)b * (NNODES * INDIM) + leaf * INDIM + k0 + k];
        }
        #pragma unroll
        for (int j = 0; j < 5; j++) {
            int lin = t + 256 * j;
            int k = lin >> 6, n = lin & 63;
            int ncol = n_base + n;
            Bs[k][n] = (ncol < 900) ? Wfioux[(size_t)(k0 + k) * 1200 + 300 + ncol] : 0.f;
        }
        __syncthreads();
        #pragma unroll
        for (int k = 0; k < 20; k++) {
            float4 a4 = *(const float4*)&As[k][ty * 4];
            float4 b4 = *(const float4*)&Bs[k][tx * 4];
            float av[4] = {a4.x, a4.y, a4.z, a4.w};
            float bv[4] = {b4.x, b4.y, b4.z, b4.w};
            #pragma unroll
            for (int i = 0; i < 4; i++)
                #pragma unroll
                for (int jj = 0; jj < 4; jj++)
                    acc[i][jj] = fmaf(av[i], bv[jj], acc[i][jj]);
        }
        __syncthreads();
    }
    #pragma unroll
    for (int i = 0; i < 4; i++) {
        int row = m_base + ty * 4 + i;
        #pragma unroll
        for (int jj = 0; jj < 4; jj++) {
            int ncol = n_base + tx * 4 + jj;
            if (ncol < 900) g_S[(size_t)row * 900 + ncol] = acc[i][jj];
        }
    }
}

// -------- leaf pointwise: c = sig(ix)*tanh(ux); h = sig(ox)*tanh(c) --------
__global__ void leaf_pointwise(const float* __restrict__ bf) {
    int idx = blockIdx.x * blockDim.x + threadIdx.x;
    if (idx >= NLEAVES * NB * MEM) return;
    int j = idx % MEM;
    int m = idx / MEM;
    size_t s = (size_t)m * 900;
    float ix = g_S[s + j]         + bf[300 + j];
    float ox = g_S[s + 300 + j]   + bf[600 + j];
    float ux = g_S[s + 600 + j]   + bf[900 + j];
    float c = sigmoidf_(ix) * tanhf(ux);
    float h = sigmoidf_(ox) * tanhf(c);
    g_C[idx] = c;    // node = m/128, layout matches exactly
    g_H[idx] = h;
}

// -------- internal GEMM: S[m,n] = [H[li]|H[ri]][b,:] @ Wcomb[:,n] --------
// m = local_node*128 + b within level, K = 600, N = 1500
__global__ __launch_bounds__(256) void internal_gemm(const int* __restrict__ left_idx,
                                                     const int* __restrict__ right_idx,
                                                     int node_base) {
    __shared__ float As[20][64];
    __shared__ float Bs[20][64];
    const int m_base = blockIdx.y * 64;
    const int n_base = blockIdx.x * 64;
    const int node = node_base + (m_base >> 7);   // 64-row tile lies in one node
    const int li = left_idx[node];
    const int ri = right_idx[node];
    const float* HL = g_H + (size_t)li * NB * MEM;
    const float* HR = g_H + (size_t)ri * NB * MEM;
    const int t = threadIdx.x;
    const int ty = t >> 4, tx = t & 15;
    float acc[4][4] = {};

    for (int k0 = 0; k0 < 600; k0 += 20) {
        const float* Hs = (k0 < 300) ? HL : HR;    // 20 | 300, tile uniform
        int koff = (k0 < 300) ? k0 : (k0 - 300);
        #pragma unroll
        for (int j = 0; j < 5; j++) {
            int lin = t + 256 * j;
            int m = lin / 20, k = lin % 20;
            int b = (m_base + m) & 127;
            As[k][m] = Hs[b * MEM + koff + k];
        }
        #pragma unroll
        for (int j = 0; j < 5; j++) {
            int lin = t + 256 * j;
            int k = lin >> 6, n = lin & 63;
            int ncol = n_base + n;
            Bs[k][n] = (ncol < 1500) ? g_Wcomb[(k0 + k) * 1500 + ncol] : 0.f;
        }
        __syncthreads();
        #pragma unroll
        for (int k = 0; k < 20; k++) {
            float4 a4 = *(const float4*)&As[k][ty * 4];
            float4 b4 = *(const float4*)&Bs[k][tx * 4];
            float av[4] = {a4.x, a4.y, a4.z, a4.w};
            float bv[4] = {b4.x, b4.y, b4.z, b4.w};
            #pragma unroll
            for (int i = 0; i < 4; i++)
                #pragma unroll
                for (int jj = 0; jj < 4; jj++)
                    acc[i][jj] = fmaf(av[i], bv[jj], acc[i][jj]);
        }
        __syncthreads();
    }
    #pragma unroll
    for (int i = 0; i < 4; i++) {
        int row = m_base + ty * 4 + i;
        #pragma unroll
        for (int jj = 0; jj < 4; jj++) {
            int ncol = n_base + tx * 4 + jj;
            if (ncol < 1500) g_S[(size_t)row * 1500 + ncol] = acc[i][jj];
        }
    }
}

// -------- internal pointwise --------
__global__ void internal_pointwise(const float* __restrict__ bf,
                                   const int* __restrict__ left_idx,
                                   const int* __restrict__ right_idx,
                                   int node_base, int count) {
    int idx = blockIdx.x * blockDim.x + threadIdx.x;
    if (idx >= count * NB * MEM) return;
    int j = idx % MEM;
    int r = idx / MEM;            // local_node*128 + b
    int b = r & 127;
    int node = node_base + (r >> 7);
    int li = left_idx[node];
    int ri = right_idx[node];
    size_t s = (size_t)r * 1500;
    float ig = sigmoidf_(g_S[s + j]          + bf[300 + j]);
    float og = sigmoidf_(g_S[s + 300 + j]    + bf[600 + j]);
    float ug = tanhf    (g_S[s + 600 + j]    + bf[900 + j]);
    float fl = sigmoidf_(g_S[s + 900 + j]    + bf[j]);
    float fr = sigmoidf_(g_S[s + 1200 + j]   + bf[j]);
    float cl = g_C[((size_t)li * NB + b) * MEM + j];
    float cr = g_C[((size_t)ri * NB + b) * MEM + j];
    float c = ig * ug + fl * cl + fr * cr;
    float h = og * tanhf(c);
    size_t o = ((size_t)node * NB + b) * MEM + j;
    g_C[o] = c;
    g_H[o] = h;
}

// -------- emit root (c, h) --------
__global__ void copy_out(float* __restrict__ out) {
    int idx = blockIdx.x * blockDim.x + threadIdx.x;
    if (idx >= 2 * NB * MEM) return;
    size_t root = (size_t)(NNODES - 1) * NB * MEM;
    out[idx] = (idx < NB * MEM) ? g_C[root + idx] : g_H[root + idx - NB * MEM];
}

extern "C" void kernel_launch(void* const* d_in, const int* in_sizes, int n_in,
                              void* d_out, int out_size) {
    const float* inputs   = (const float*)d_in[0];
    const float* Wfioux   = (const float*)d_in[1];
    const float* b_fioux  = (const float*)d_in[2];
    const float* Wiouh    = (const float*)d_in[3];
    const float* Wfh      = (const float*)d_in[4];
    const int*   left_idx = (const int*)d_in[5];
    const int*   right_idx= (const int*)d_in[6];
    float* out = (float*)d_out;

    build_wcomb<<<(600 * 1500 + 255) / 256, 256>>>(Wiouh, Wfh);

    // leaf stage: GEMM [65536 x 300] @ [300 x 900] then gates
    leaf_gemm<<<dim3(15, 1024), 256>>>(inputs, Wfioux);
    leaf_pointwise<<<(NLEAVES * NB * MEM + 255) / 256, 256>>>(b_fioux);

    // internal levels: 256, 128, ..., 1 nodes
    int base = NLEAVES;
    for (int k = NLEAVES / 2; k >= 1; k >>= 1) {
        internal_gemm<<<dim3(24, 2 * k), 256>>>(left_idx, right_idx, base);
        internal_pointwise<<<(k * NB * MEM + 255) / 256, 256>>>(b_fioux, left_idx, right_idx, base, k);
        base += k;
    }

    copy_out<<<(2 * NB * MEM + 255) / 256, 256>>>(out);
}

// round 4
// speedup vs baseline: 4.8793x; 4.8793x over previous
#include <cuda_runtime.h>
#include <math.h>
#include <stdint.h>

#define NB      128
#define NNODES  1023
#define NLEAVES 512
#define MEM     300
#define INDIM   300

// ---------------- static device scratch (no allocs allowed) ----------------
__device__ float g_C[(size_t)NNODES * NB * MEM];
__device__ float g_H[(size_t)NNODES * NB * MEM];
// gate-blocked transposed weights:
// internal: [10 jtiles][5 gates][32 jl][608 k]  = 1600 x 608
// leaf:     [10 jtiles][3 gates][32 jl][320 k]  =  960 x 320
__device__ float g_WT_int[1600 * 608];
__device__ float g_WT_leaf[960 * 320];

__device__ __forceinline__ float sigmoidf_(float x) { return 1.0f / (1.0f + __expf(-x)); }

__device__ __forceinline__ uint32_t smem_u32(const void* p) {
    uint32_t a;
    asm("{ .reg .u64 t; cvta.to.shared.u64 t, %1; cvt.u32.u64 %0, t; }" : "=r"(a) : "l"(p));
    return a;
}
__device__ __forceinline__ void cp_async16(uint32_t s, const void* g) {
    asm volatile("cp.async.ca.shared.global [%0], [%1], 16;" :: "r"(s), "l"(g) : "memory");
}
__device__ __forceinline__ void cp_commit() {
    asm volatile("cp.async.commit_group;" ::: "memory");
}
__device__ __forceinline__ void cp_wait1() {
    asm volatile("cp.async.wait_group 1;" ::: "memory");
}
__device__ __forceinline__ void cp_wait0() {
    asm volatile("cp.async.wait_group 0;" ::: "memory");
}
// tf32 m16n8k8: D(f32) += A(tf32) * B(tf32); raw fp32 bits (HW truncates mantissa)
__device__ __forceinline__ void mma_tf32(float* c, const uint32_t* a, uint32_t b0, uint32_t b1) {
    asm volatile(
        "mma.sync.aligned.m16n8k8.row.col.f32.tf32.tf32.f32 "
        "{%0,%1,%2,%3}, {%4,%5,%6,%7}, {%8,%9}, {%0,%1,%2,%3};"
        : "+f"(c[0]), "+f"(c[1]), "+f"(c[2]), "+f"(c[3])
        : "r"(a[0]), "r"(a[1]), "r"(a[2]), "r"(a[3]), "r"(b0), "r"(b1));
}

// ---------------- weight rearrangement ----------------
__global__ void build_wt_int(const float* __restrict__ Wiouh, const float* __restrict__ Wfh) {
    int idx = blockIdx.x * blockDim.x + threadIdx.x;
    if (idx >= 1600 * 608) return;
    int n = idx / 608, k = idx % 608;
    int tile = n / 160, rem = n % 160;
    int g = rem / 32, jl = rem % 32;
    int j = tile * 32 + jl;
    float v = 0.f;
    if (j < 300 && k < 600)
        v = (g < 3) ? Wiouh[k * 900 + g * 300 + j] : Wfh[k * 600 + (g - 3) * 300 + j];
    g_WT_int[idx] = v;
}
__global__ void build_wt_leaf(const float* __restrict__ Wfioux) {
    int idx = blockIdx.x * blockDim.x + threadIdx.x;
    if (idx >= 960 * 320) return;
    int n = idx / 320, k = idx % 320;
    int tile = n / 96, rem = n % 96;
    int g = rem / 32, jl = rem % 32;
    int j = tile * 32 + jl;
    g_WT_leaf[idx] = (j < 300 && k < 300) ? Wfioux[k * 1200 + (g + 1) * 300 + j] : 0.f;
}

// ---------------- internal-level fused GEMM+gates ----------------
// grid (10, k). 256 threads = 8 warps: wm = w%4 (rows wm*32), wn = w/4 (jl half).
// A: [128 x 608] = [H[li] | H[ri]] row-major.  B: WT slice [160 n x 608 k].
// SMEM float layout: A0 @0 (128x36), A1 @4608, B0 @9216 (160x36), B1 @14976.
#define IA0 0
#define IA1 4608
#define IB0 9216
#define IB1 14976
#define ISMEM_F 20736   // 82944 bytes

__global__ __launch_bounds__(256) void internal_tc(
    const int* __restrict__ left_idx, const int* __restrict__ right_idx,
    const float* __restrict__ bf, int node_base)
{
    extern __shared__ float sm[];
    const uint32_t sb = smem_u32(sm);
    const int tid  = threadIdx.x;
    const int w    = tid >> 5, lane = tid & 31;
    const int wm   = w & 3, wn = w >> 2;
    const int node = node_base + blockIdx.y;
    const int li = left_idx[node], ri = right_idx[node];
    const int jbase = blockIdx.x * 32;
    const int jcount = (300 - jbase < 32) ? (300 - jbase) : 32;

    const float* HL = g_H + (size_t)li * (NB * MEM);
    const float* HR = g_H + (size_t)ri * (NB * MEM);
    const float* WT = g_WT_int + (size_t)blockIdx.x * 160 * 608;

    float acc[2][10][4];
    #pragma unroll
    for (int mt = 0; mt < 2; mt++)
        #pragma unroll
        for (int t = 0; t < 10; t++)
            #pragma unroll
            for (int e = 0; e < 4; e++) acc[mt][t][e] = 0.f;

    const int NCH = 19;  // K = 608
    // ---- staging lambda-ish macro ----
    #define STAGE_INT(CH, AOFF, BOFF) do {                                         \
        int kc = (CH) * 32;                                                        \
        _Pragma("unroll")                                                          \
        for (int i = 0; i < 4; i++) {            /* A: 1024 16B groups */          \
            int v = i * 256 + tid;                                                 \
            int m = v >> 3, kq = v & 7;                                            \
            int kg = kc + kq * 4;                                                  \
            uint32_t dst = sb + ((AOFF) + m * 36 + kq * 4) * 4;                    \
            if (kg < 300)      cp_async16(dst, HL + (size_t)m * MEM + kg);         \
            else if (kg < 600) cp_async16(dst, HR + (size_t)m * MEM + kg - 300);   \
            else *(float4*)(sm + (AOFF) + m * 36 + kq * 4) = make_float4(0,0,0,0); \
        }                                                                          \
        _Pragma("unroll")                                                          \
        for (int i = 0; i < 5; i++) {            /* B: 1280 16B groups */          \
            int v = i * 256 + tid;                                                 \
            int n = v >> 3, kq = v & 7;                                            \
            uint32_t dst = sb + ((BOFF) + n * 36 + kq * 4) * 4;                    \
            cp_async16(dst, WT + (size_t)n * 608 + kc + kq * 4);                   \
        }                                                                          \
        cp_commit();                                                               \
    } while (0)

    STAGE_INT(0, IA0, IB0);
    #pragma unroll 1
    for (int ch = 0; ch < NCH; ch++) {
        if (ch + 1 < NCH) {
            if ((ch + 1) & 1) STAGE_INT(ch + 1, IA1, IB1);
            else              STAGE_INT(ch + 1, IA0, IB0);
            cp_wait1();
        } else {
            cp_wait0();
        }
        __syncthreads();
        const float* Ab = sm + ((ch & 1) ? IA1 : IA0);
        const float* Bb = sm + ((ch & 1) ? IB1 : IB0);
        #pragma unroll
        for (int ks = 0; ks < 4; ks++) {
            uint32_t a[2][4];
            int c0 = ks * 8 + (lane & 3);
            #pragma unroll
            for (int mt = 0; mt < 2; mt++) {
                int r = wm * 32 + mt * 16 + (lane >> 2);
                a[mt][0] = __float_as_uint(Ab[r * 36 + c0]);
                a[mt][1] = __float_as_uint(Ab[(r + 8) * 36 + c0]);
                a[mt][2] = __float_as_uint(Ab[r * 36 + c0 + 4]);
                a[mt][3] = __float_as_uint(Ab[(r + 8) * 36 + c0 + 4]);
            }
            #pragma unroll
            for (int t = 0; t < 10; t++) {
                int g = t >> 1, jt = t & 1;
                int n = g * 32 + wn * 16 + jt * 8 + (lane >> 2);
                uint32_t b0 = __float_as_uint(Bb[n * 36 + c0]);
                uint32_t b1 = __float_as_uint(Bb[n * 36 + c0 + 4]);
                mma_tf32(acc[0][t], a[0], b0, b1);
                mma_tf32(acc[1][t], a[1], b0, b1);
            }
        }
        __syncthreads();
    }
    #undef STAGE_INT

    // ---- fused epilogue: gates fully in registers ----
    #pragma unroll
    for (int mt = 0; mt < 2; mt++) {
        #pragma unroll
        for (int jt = 0; jt < 2; jt++) {
            #pragma unroll
            for (int e = 0; e < 4; e++) {
                int jl = wn * 16 + jt * 8 + (lane & 3) * 2 + (e & 1);
                if (jl >= jcount) continue;
                int j = jbase + jl;
                int m = wm * 32 + mt * 16 + (lane >> 2) + ((e >> 1) * 8);
                float gi = sigmoidf_(acc[mt][0 + jt][e] + bf[300 + j]);
                float go = sigmoidf_(acc[mt][2 + jt][e] + bf[600 + j]);
                float gu = tanhf    (acc[mt][4 + jt][e] + bf[900 + j]);
                float fl = sigmoidf_(acc[mt][6 + jt][e] + bf[j]);
                float fr = sigmoidf_(acc[mt][8 + jt][e] + bf[j]);
                float cl = g_C[((size_t)li * NB + m) * MEM + j];
                float cr = g_C[((size_t)ri * NB + m) * MEM + j];
                float c = gi * gu + fl * cl + fr * cr;
                float h = go * tanhf(c);
                g_C[((size_t)node * NB + m) * MEM + j] = c;
                g_H[((size_t)node * NB + m) * MEM + j] = h;
            }
        }
    }
}

// ---------------- leaf fused GEMM+gates ----------------
// grid (10, 512). A: inputs rows (batch) for one leaf, K=320. B: 96 x 320. 3 gates.
#define LA0 0
#define LA1 4608
#define LB0 9216
#define LB1 12672
#define LSMEM_F 16128   // 64512 bytes

__global__ __launch_bounds__(256) void leaf_tc(
    const float* __restrict__ inputs, const float* __restrict__ bf)
{
    extern __shared__ float sm[];
    const uint32_t sb = smem_u32(sm);
    const int tid  = threadIdx.x;
    const int w    = tid >> 5, lane = tid & 31;
    const int wm   = w & 3, wn = w >> 2;
    const int leaf = blockIdx.y;
    const int jbase = blockIdx.x * 32;
    const int jcount = (300 - jbase < 32) ? (300 - jbase) : 32;

    const float* X  = inputs + (size_t)leaf * INDIM;          // + m*(NNODES*INDIM)
    const float* WT = g_WT_leaf + (size_t)blockIdx.x * 96 * 320;

    float acc[2][6][4];
    #pragma unroll
    for (int mt = 0; mt < 2; mt++)
        #pragma unroll
        for (int t = 0; t < 6; t++)
            #pragma unroll
            for (int e = 0; e < 4; e++) acc[mt][t][e] = 0.f;

    const int NCH = 10;  // K = 320
    #define STAGE_LEAF(CH, AOFF, BOFF) do {                                        \
        int kc = (CH) * 32;                                                        \
        _Pragma("unroll")                                                          \
        for (int i = 0; i < 4; i++) {                                              \
            int v = i * 256 + tid;                                                 \
            int m = v >> 3, kq = v & 7;                                            \
            int kg = kc + kq * 4;                                                  \
            uint32_t dst = sb + ((AOFF) + m * 36 + kq * 4) * 4;                    \
            if (kg < 300) cp_async16(dst, X + (size_t)m * (NNODES * INDIM) + kg);  \
            else *(float4*)(sm + (AOFF) + m * 36 + kq * 4) = make_float4(0,0,0,0); \
        }                                                                          \
        _Pragma("unroll")                                                          \
        for (int i = 0; i < 3; i++) {            /* B: 768 16B groups */           \
            int v = i * 256 + tid;                                                 \
            int n = v >> 3, kq = v & 7;                                            \
            uint32_t dst = sb + ((BOFF) + n * 36 + kq * 4) * 4;                    \
            cp_async16(dst, WT + (size_t)n * 320 + kc + kq * 4);                   \
        }                                                                          \
        cp_commit();                                                               \
    } while (0)

    STAGE_LEAF(0, LA0, LB0);
    #pragma unroll 1
    for (int ch = 0; ch < NCH; ch++) {
        if (ch + 1 < NCH) {
            if ((ch + 1) & 1) STAGE_LEAF(ch + 1, LA1, LB1);
            else              STAGE_LEAF(ch + 1, LA0, LB0);
            cp_wait1();
        } else {
            cp_wait0();
        }
        __syncthreads();
        const float* Ab = sm + ((ch & 1) ? LA1 : LA0);
        const float* Bb = sm + ((ch & 1) ? LB1 : LB0);
        #pragma unroll
        for (int ks = 0; ks < 4; ks++) {
            uint32_t a[2][4];
            int c0 = ks * 8 + (lane & 3);
            #pragma unroll
            for (int mt = 0; mt < 2; mt++) {
                int r = wm * 32 + mt * 16 + (lane >> 2);
                a[mt][0] = __float_as_uint(Ab[r * 36 + c0]);
                a[mt][1] = __float_as_uint(Ab[(r + 8) * 36 + c0]);
                a[mt][2] = __float_as_uint(Ab[r * 36 + c0 + 4]);
                a[mt][3] = __float_as_uint(Ab[(r + 8) * 36 + c0 + 4]);
            }
            #pragma unroll
            for (int t = 0; t < 6; t++) {
                int g = t >> 1, jt = t & 1;
                int n = g * 32 + wn * 16 + jt * 8 + (lane >> 2);
                uint32_t b0 = __float_as_uint(Bb[n * 36 + c0]);
                uint32_t b1 = __float_as_uint(Bb[n * 36 + c0 + 4]);
                mma_tf32(acc[0][t], a[0], b0, b1);
                mma_tf32(acc[1][t], a[1], b0, b1);
            }
        }
        __syncthreads();
    }
    #undef STAGE_LEAF

    #pragma unroll
    for (int mt = 0; mt < 2; mt++) {
        #pragma unroll
        for (int jt = 0; jt < 2; jt++) {
            #pragma unroll
            for (int e = 0; e < 4; e++) {
                int jl = wn * 16 + jt * 8 + (lane & 3) * 2 + (e & 1);
                if (jl >= jcount) continue;
                int j = jbase + jl;
                int m = wm * 32 + mt * 16 + (lane >> 2) + ((e >> 1) * 8);
                float gi = sigmoidf_(acc[mt][0 + jt][e] + bf[300 + j]);
                float go = sigmoidf_(acc[mt][2 + jt][e] + bf[600 + j]);
                float gu = tanhf    (acc[mt][4 + jt][e] + bf[900 + j]);
                float c = gi * gu;
                float h = go * tanhf(c);
                g_C[((size_t)leaf * NB + m) * MEM + j] = c;
                g_H[((size_t)leaf * NB + m) * MEM + j] = h;
            }
        }
    }
}

// ---------------- emit root (c, h) ----------------
__global__ void copy_out(float* __restrict__ out) {
    int idx = blockIdx.x * blockDim.x + threadIdx.x;
    if (idx >= 2 * NB * MEM) return;
    size_t root = (size_t)(NNODES - 1) * NB * MEM;
    out[idx] = (idx < NB * MEM) ? g_C[root + idx] : g_H[root + idx - NB * MEM];
}

extern "C" void kernel_launch(void* const* d_in, const int* in_sizes, int n_in,
                              void* d_out, int out_size) {
    const float* inputs   = (const float*)d_in[0];
    const float* Wfioux   = (const float*)d_in[1];
    const float* b_fioux  = (const float*)d_in[2];
    const float* Wiouh    = (const float*)d_in[3];
    const float* Wfh      = (const float*)d_in[4];
    const int*   left_idx = (const int*)d_in[5];
    const int*   right_idx= (const int*)d_in[6];
    float* out = (float*)d_out;

    cudaFuncSetAttribute(internal_tc, cudaFuncAttributeMaxDynamicSharedMemorySize,
                         ISMEM_F * 4);
    cudaFuncSetAttribute(leaf_tc, cudaFuncAttributeMaxDynamicSharedMemorySize,
                         LSMEM_F * 4);

    build_wt_int<<<(1600 * 608 + 255) / 256, 256>>>(Wiouh, Wfh);
    build_wt_leaf<<<(960 * 320 + 255) / 256, 256>>>(Wfioux);

    leaf_tc<<<dim3(10, NLEAVES), 256, LSMEM_F * 4>>>(inputs, b_fioux);

    int base = NLEAVES;
    for (int k = NLEAVES / 2; k >= 1; k >>= 1) {
        internal_tc<<<dim3(10, k), 256, ISMEM_F * 4>>>(left_idx, right_idx, b_fioux, base);
        base += k;
    }
    copy_out<<<(2 * NB * MEM + 255) / 256, 256>>>(out);
}